// round 14
// baseline (speedup 1.0000x reference)
#include <cuda_runtime.h>

// WideComponent: out[b] = emb_user[u[b]] + emb_item[i[b]] + emb_cat[c[b]]
//                       + cross_w[u[b]*D_CAT + c[b]]
//                       + cross_w[OFF_IC + i[b]*D_CAT + c[b]]
// D_USER=100000, D_ITEM=50000, D_CAT=1000, OFF_IC = 100,000,000. B = 16384.
//
// FINAL (converged). Overhead-bound kernel at the graph-replay floor. Nine
// valid measurements across four kernel shapes all land at 6.7 +/- 0.3 us;
// three identical-source reruns span 6.624-6.912 us, bounding the noise at
// +/-0.3 us and proving all inter-variant deltas were noise. Warm device
// work is ~0.4 us (index load -> data-dependent gather, two L2 hops over a
// replay-resident ~2.5 MB working set); the remaining ~6 us is fixed
// per-replay graph-launch latency (ncu across 8 profiles: DRAM ~8%,
// issue ~1%, all compute pipes idle). Exhausted neutral levers: CTA
// geometry (64x256 / 128x128 / 32x128), VEC 1/4, gather issue order,
// predication. Measured-best config: 128 CTAs x 128 threads (full SM
// coverage, single wave), 5 independent gathers front-batched per thread
// (MLP=5), 22 regs.

static constexpr int D_CAT  = 1000;
static constexpr int OFF_IC = 100000 * D_CAT;  // 100,000,000

__global__ void __launch_bounds__(128) wide_kernel(
    const int* __restrict__ user_id,
    const int* __restrict__ item_id,
    const int* __restrict__ category,
    const float* __restrict__ emb_user,
    const float* __restrict__ emb_item,
    const float* __restrict__ emb_cat,
    const float* __restrict__ cross_w,
    float* __restrict__ out,
    int n)
{
    int b = blockIdx.x * blockDim.x + threadIdx.x;
    if (b >= n) return;

    // Three independent index loads (coalesced, L2-hot across replays)
    int u = __ldg(&user_id[b]);
    int i = __ldg(&item_id[b]);
    int c = __ldg(&category[b]);

    // Five independent gathers, front-batched by ptxas (MLP=5).
    float wu = __ldg(&emb_user[u]);
    float wi = __ldg(&emb_item[i]);
    float wc = __ldg(&emb_cat[c]);
    float xu = __ldg(&cross_w[u * D_CAT + c]);
    float xi = __ldg(&cross_w[OFF_IC + i * D_CAT + c]);

    out[b] = wu + wi + wc + xu + xi;
}

extern "C" void kernel_launch(void* const* d_in, const int* in_sizes, int n_in,
                              void* d_out, int out_size)
{
    const int*   user_id  = (const int*)  d_in[0];
    const int*   item_id  = (const int*)  d_in[1];
    const int*   category = (const int*)  d_in[2];
    const float* emb_user = (const float*)d_in[3];
    const float* emb_item = (const float*)d_in[4];
    const float* emb_cat  = (const float*)d_in[5];
    const float* cross_w  = (const float*)d_in[6];
    float*       out      = (float*)d_out;

    int n = in_sizes[0];  // B = 16384
    int threads = 128;    // 128 CTAs -> near-full SM coverage, single wave
    int blocks = (n + threads - 1) / threads;
    wide_kernel<<<blocks, threads>>>(user_id, item_id, category,
                                     emb_user, emb_item, emb_cat, cross_w,
                                     out, n);
}

// round 15
// speedup vs baseline: 1.0337x; 1.0337x over previous
#include <cuda_runtime.h>

// WideComponent: out[b] = emb_user[u[b]] + emb_item[i[b]] + emb_cat[c[b]]
//                       + cross_w[u[b]*D_CAT + c[b]]
//                       + cross_w[OFF_IC + i[b]*D_CAT + c[b]]
// D_USER=100000, D_ITEM=50000, D_CAT=1000, OFF_IC = 100,000,000. B = 16384.
//
// FINAL (converged). Overhead-bound kernel at the graph-replay floor. Ten
// valid measurements across four kernel shapes all land at 6.7 +/- 0.3 us;
// four identical-source reruns span the full 6.624-6.912 us range, proving
// the measurement is a bimodal noise distribution (32 ns timer quanta)
// over a fixed-overhead kernel. Warm device work is ~0.4 us (index load ->
// data-dependent gather, two L2 hops over a replay-resident ~2.5 MB
// working set); the remaining ~6 us is fixed per-replay graph-launch
// latency (ncu across 9 profiles: DRAM ~8%, issue ~1%, all compute pipes
// idle). Exhausted neutral levers: CTA geometry (64x256 / 128x128 /
// 32x128), VEC 1/4, gather issue order, predication. Measured-best config:
// 128 CTAs x 128 threads (full SM coverage, single wave), 5 independent
// gathers front-batched per thread (MLP=5), 22 regs.

static constexpr int D_CAT  = 1000;
static constexpr int OFF_IC = 100000 * D_CAT;  // 100,000,000

__global__ void __launch_bounds__(128) wide_kernel(
    const int* __restrict__ user_id,
    const int* __restrict__ item_id,
    const int* __restrict__ category,
    const float* __restrict__ emb_user,
    const float* __restrict__ emb_item,
    const float* __restrict__ emb_cat,
    const float* __restrict__ cross_w,
    float* __restrict__ out,
    int n)
{
    int b = blockIdx.x * blockDim.x + threadIdx.x;
    if (b >= n) return;

    // Three independent index loads (coalesced, L2-hot across replays)
    int u = __ldg(&user_id[b]);
    int i = __ldg(&item_id[b]);
    int c = __ldg(&category[b]);

    // Five independent gathers, front-batched by ptxas (MLP=5).
    float wu = __ldg(&emb_user[u]);
    float wi = __ldg(&emb_item[i]);
    float wc = __ldg(&emb_cat[c]);
    float xu = __ldg(&cross_w[u * D_CAT + c]);
    float xi = __ldg(&cross_w[OFF_IC + i * D_CAT + c]);

    out[b] = wu + wi + wc + xu + xi;
}

extern "C" void kernel_launch(void* const* d_in, const int* in_sizes, int n_in,
                              void* d_out, int out_size)
{
    const int*   user_id  = (const int*)  d_in[0];
    const int*   item_id  = (const int*)  d_in[1];
    const int*   category = (const int*)  d_in[2];
    const float* emb_user = (const float*)d_in[3];
    const float* emb_item = (const float*)d_in[4];
    const float* emb_cat  = (const float*)d_in[5];
    const float* cross_w  = (const float*)d_in[6];
    float*       out      = (float*)d_out;

    int n = in_sizes[0];  // B = 16384
    int threads = 128;    // 128 CTAs -> near-full SM coverage, single wave
    int blocks = (n + threads - 1) / threads;
    wide_kernel<<<blocks, threads>>>(user_id, item_id, category,
                                     emb_user, emb_item, emb_cat, cross_w,
                                     out, n);
}

// round 17
// speedup vs baseline: 1.0914x; 1.0558x over previous
#include <cuda_runtime.h>

// WideComponent: out[b] = emb_user[u[b]] + emb_item[i[b]] + emb_cat[c[b]]
//                       + cross_w[u[b]*D_CAT + c[b]]
//                       + cross_w[OFF_IC + i[b]*D_CAT + c[b]]
// D_USER=100000, D_ITEM=50000, D_CAT=1000, OFF_IC = 100,000,000. B = 16384.
//
// FINAL (converged). Overhead-bound kernel at the graph-replay floor.
// Eleven valid measurements across four kernel shapes all land at
// 6.7 +/- 0.3 us; five identical-source reruns span the full 6.624-6.912
// range, proving the measurement is a bimodal noise distribution over a
// fixed-overhead kernel. Warm device work is ~0.4 us (index load ->
// data-dependent gather, two L2 hops over a replay-resident ~2.5 MB
// working set); the remaining ~6 us is fixed per-replay graph-launch
// latency (ncu across 10 profiles: DRAM 7-8.6%, issue 1-2%, all compute
// pipes idle; cold dur itself varies 7.4-9.0 us run-to-run). Exhausted
// neutral levers: CTA geometry (64x256 / 128x128 / 32x128), VEC 1/4,
// gather issue order, predication. Measured-best config: 128 CTAs x 128
// threads (full SM coverage, single wave), 5 independent gathers
// front-batched per thread (MLP=5), 22 regs.

static constexpr int D_CAT  = 1000;
static constexpr int OFF_IC = 100000 * D_CAT;  // 100,000,000

__global__ void __launch_bounds__(128) wide_kernel(
    const int* __restrict__ user_id,
    const int* __restrict__ item_id,
    const int* __restrict__ category,
    const float* __restrict__ emb_user,
    const float* __restrict__ emb_item,
    const float* __restrict__ emb_cat,
    const float* __restrict__ cross_w,
    float* __restrict__ out,
    int n)
{
    int b = blockIdx.x * blockDim.x + threadIdx.x;
    if (b >= n) return;

    // Three independent index loads (coalesced, L2-hot across replays)
    int u = __ldg(&user_id[b]);
    int i = __ldg(&item_id[b]);
    int c = __ldg(&category[b]);

    // Five independent gathers, front-batched by ptxas (MLP=5).
    float wu = __ldg(&emb_user[u]);
    float wi = __ldg(&emb_item[i]);
    float wc = __ldg(&emb_cat[c]);
    float xu = __ldg(&cross_w[u * D_CAT + c]);
    float xi = __ldg(&cross_w[OFF_IC + i * D_CAT + c]);

    out[b] = wu + wi + wc + xu + xi;
}

extern "C" void kernel_launch(void* const* d_in, const int* in_sizes, int n_in,
                              void* d_out, int out_size)
{
    const int*   user_id  = (const int*)  d_in[0];
    const int*   item_id  = (const int*)  d_in[1];
    const int*   category = (const int*)  d_in[2];
    const float* emb_user = (const float*)d_in[3];
    const float* emb_item = (const float*)d_in[4];
    const float* emb_cat  = (const float*)d_in[5];
    const float* cross_w  = (const float*)d_in[6];
    float*       out      = (float*)d_out;

    int n = in_sizes[0];  // B = 16384
    int threads = 128;    // 128 CTAs -> near-full SM coverage, single wave
    int blocks = (n + threads - 1) / threads;
    wide_kernel<<<blocks, threads>>>(user_id, item_id, category,
                                     emb_user, emb_item, emb_cat, cross_w,
                                     out, n);
}